// round 17
// baseline (speedup 1.0000x reference)
#include <cuda_runtime.h>
#include <cuda_fp16.h>
#include <cstdint>

// x[32768,2048] fp32, bank[20,2048] fp32 -> out[32768,2048] fp32
constexpr int FEA    = 2048;
constexpr int NBANK  = 20;
constexpr int RU     = 16;            // rows per unit
constexpr int KC     = 32;            // k cols per chunk
constexpr int NCHK   = FEA / KC;      // 64 chunks per unit
constexpr int UPP    = 2;             // units per pair
constexpr int DEPTH  = 6;             // front cp.async ring slots
constexpr int NTH    = 512;           // 8 front + 8 back warps
constexpr float LAMBDA = 0.0025f;

// SMEM map (197632 B, 1 CTA/SM)
constexpr int SM_BANK = 0;                         // [20 j][2048 k] fp16 swz
constexpr int BANKB   = NBANK * 4096;              // 81920
constexpr int SM_ZP   = BANKB;                     // 1KB zero page
constexpr int SM_XR   = SM_ZP + 1024;              // 8 fronts x 6 x 2KB
constexpr int SLOTB   = RU * KC * 4;               // 2048
constexpr int SM_ATT  = SM_XR + 8 * DEPTH * SLOTB; // 181248: 8 pairs x 2 x 1KB
constexpr int SM_TOTAL = SM_ATT + 8 * UPP * 1024;  // 197632

__device__ __forceinline__ uint32_t s2u(const void* p) {
    uint32_t a;
    asm("{ .reg .u64 t; cvta.to.shared.u64 t, %1; cvt.u32.u64 %0, t; }"
        : "=r"(a) : "l"(p));
    return a;
}
__device__ __forceinline__ void ldsm4(uint32_t a, uint32_t& r0, uint32_t& r1,
                                      uint32_t& r2, uint32_t& r3) {
    asm volatile("ldmatrix.sync.aligned.m8n8.x4.shared.b16 {%0,%1,%2,%3}, [%4];"
                 : "=r"(r0), "=r"(r1), "=r"(r2), "=r"(r3) : "r"(a));
}
__device__ __forceinline__ void ldsm4t(uint32_t a, uint32_t& r0, uint32_t& r1,
                                       uint32_t& r2, uint32_t& r3) {
    asm volatile("ldmatrix.sync.aligned.m8n8.x4.trans.shared.b16 {%0,%1,%2,%3}, [%4];"
                 : "=r"(r0), "=r"(r1), "=r"(r2), "=r"(r3) : "r"(a));
}
__device__ __forceinline__ void mma16816(float& d0, float& d1, float& d2, float& d3,
                                         uint32_t a0, uint32_t a1, uint32_t a2, uint32_t a3,
                                         uint32_t b0, uint32_t b1) {
    asm volatile(
        "mma.sync.aligned.m16n8k16.row.col.f32.f16.f16.f32 "
        "{%0,%1,%2,%3}, {%4,%5,%6,%7}, {%8,%9}, {%0,%1,%2,%3};"
        : "+f"(d0), "+f"(d1), "+f"(d2), "+f"(d3)
        : "r"(a0), "r"(a1), "r"(a2), "r"(a3), "r"(b0), "r"(b1));
}
__device__ __forceinline__ float tanh_fast(float v) {
    float r;
    asm("tanh.approx.f32 %0, %1;" : "=f"(r) : "f"(v));
    return r;
}
__device__ __forceinline__ uint32_t h2(float lo, float hi) {
    __half2 h = __floats2half2_rn(lo, hi);
    return *reinterpret_cast<uint32_t*>(&h);
}
__device__ __forceinline__ void cp16(uint32_t dst, const float* src) {
    asm volatile("cp.async.cg.shared.global [%0], [%1], 16;" :: "r"(dst), "l"(src));
}
__device__ __forceinline__ float2 lds64(uint32_t a) {
    float2 v;
    asm volatile("ld.shared.v2.f32 {%0,%1}, [%2];" : "=f"(v.x), "=f"(v.y) : "r"(a));
    return v;
}
__device__ __forceinline__ void sts32(uint32_t a, uint32_t v) {
    asm volatile("st.shared.b32 [%0], %1;" :: "r"(a), "r"(v) : "memory");
}
__device__ __forceinline__ void barp(int id) {   // pair barrier: 64 threads
    asm volatile("bar.sync %0, 64;" :: "r"(id) : "memory");
}
__device__ __forceinline__ float redmax4(float v) {
    v = fmaxf(v, __shfl_xor_sync(0xffffffffu, v, 1));
    v = fmaxf(v, __shfl_xor_sync(0xffffffffu, v, 2));
    return v;
}
__device__ __forceinline__ float redsum4(float v) {
    v += __shfl_xor_sync(0xffffffffu, v, 1);
    v += __shfl_xor_sync(0xffffffffu, v, 2);
    return v;
}

extern __shared__ char smc[];

__global__ void __launch_bounds__(NTH, 1)
memunit_fb(const float* __restrict__ x,
           const float* __restrict__ bank,
           float* __restrict__ out,
           int n_pairs)
{
    const uint32_t sbase = s2u(smc);
    const int tid  = threadIdx.x;
    const int warp = tid >> 5;
    const int lane = tid & 31;

    // ---- bank -> fp16 [20 j][2048 k], swizzle byte = j*4096 + (2k ^ ((j&7)<<4))
    for (int idx = tid; idx < NBANK * FEA; idx += NTH) {
        const int j = idx >> 11, k = idx & (FEA - 1);
        *reinterpret_cast<__half*>(smc + SM_BANK + j * 4096 + ((2 * k) ^ ((j & 7) << 4)))
            = __float2half(bank[idx]);
    }
    for (int i = tid; i < 1024 / 4; i += NTH)
        reinterpret_cast<uint32_t*>(smc + SM_ZP)[i] = 0u;
    __syncthreads();   // the only CTA-wide barrier

    const int p = warp & 7;                             // pair id 0..7
    const int pair_gid = (int)blockIdx.x * 8 + p;
    if (pair_gid >= n_pairs) return;
    const long pairRow = (long)pair_gid * (UPP * RU);   // 32 rows per pair
    const int barid = p + 1;

    // common fragment geometry
    const int rA  = lane >> 2;            // 0..7 (second row = rA + 8)
    const int m   = lane & 3;
    const int swj = (lane & 7) << 4;
    const bool jv = lane < NBANK;
    const uint32_t btlv = sbase + SM_BANK + lane * 4096;   // j = lane
    const uint32_t zp   = sbase + SM_ZP + (lane & 15) * 16;
    const uint32_t attb = sbase + SM_ATT + p * (UPP * 1024);

    if (warp < 8) {
        // =================== FRONT: GEMM1 + softmax + att ===================
        const bool v2 = m < 2;
        const int rsw = rA << 4;
        const uint32_t ring = sbase + SM_XR + p * (DEPTH * SLOTB);
        const int TOTC = UPP * NCHK;      // 128 flat chunks

        auto issue = [&](int gg, int slot) {
            if (gg < TOTC) {
                const uint32_t db = ring + slot * SLOTB;
                const long rb = pairRow + (long)(gg >> 6) * RU;
                const int ccol = (gg & 63) * KC;
                #pragma unroll
                for (int i = 0; i < 4; i++) {
                    const int f = i * 32 + lane;      // 16B piece 0..127
                    const int row = f >> 3, gq = f & 7;
                    cp16(db + row * 128 + ((gq * 16) ^ ((row & 7) << 4)),
                         x + (rb + row) * FEA + ccol + gq * 4);
                }
            }
            asm volatile("cp.async.commit_group;" ::: "memory");
        };

        // prologue: 5 chunks in flight
        #pragma unroll
        for (int s = 0; s < 5; s++) issue(s, s);
        int g = 0, sc = 0, si = 5;

        for (int u = 0; u < UPP; u++) {
            float d[4][4];
            #pragma unroll
            for (int b = 0; b < 4; b++)
                #pragma unroll
                for (int q = 0; q < 4; q++) d[b][q] = 0.f;

            #pragma unroll 2
            for (int c = 0; c < NCHK; c++) {
                asm volatile("cp.async.wait_group %0;" :: "n"(4) : "memory");
                __syncwarp();
                issue(g + 5, si);

                const uint32_t sb = ring + sc * SLOTB;
                #pragma unroll
                for (int ks = 0; ks < 2; ks++) {
                    const int cb = ks * 64 + m * 8;
                    const float2 f0 = lds64(sb + rA * 128 + (cb ^ rsw));
                    const float2 f1 = lds64(sb + (rA + 8) * 128 + (cb ^ rsw));
                    const float2 f2 = lds64(sb + rA * 128 + ((cb + 32) ^ rsw));
                    const float2 f3 = lds64(sb + (rA + 8) * 128 + ((cb + 32) ^ rsw));
                    const uint32_t a0 = h2(f0.x, f0.y);
                    const uint32_t a1 = h2(f1.x, f1.y);
                    const uint32_t a2 = h2(f2.x, f2.y);
                    const uint32_t a3 = h2(f3.x, f3.y);

                    const int colb = c * 64 + ks * 32;
                    uint32_t B0[4], B1[4];
                    ldsm4(jv ? btlv + (colb ^ swj) : zp,        B0[0], B0[1], B0[2], B0[3]);
                    ldsm4(jv ? btlv + ((colb + 16) ^ swj) : zp, B1[0], B1[1], B1[2], B1[3]);
                    #pragma unroll
                    for (int b = 0; b < 4; b++)
                        mma16816(d[b][0], d[b][1], d[b][2], d[b][3],
                                 a0, a1, a2, a3, B0[b], B1[b]);
                }
                g++;
                sc = (sc + 1 == DEPTH) ? 0 : sc + 1;
                si = (si + 1 == DEPTH) ? 0 : si + 1;
            }

            // ---- in-warp softmax -> softshrink -> softmax ------------------
            float AA[6], AB[6];
            {
                float mA = fmaxf(fmaxf(d[0][0], d[0][1]), fmaxf(d[1][0], d[1][1]));
                float mB = fmaxf(fmaxf(d[0][2], d[0][3]), fmaxf(d[1][2], d[1][3]));
                if (v2) {
                    mA = fmaxf(mA, fmaxf(d[2][0], d[2][1]));
                    mB = fmaxf(mB, fmaxf(d[2][2], d[2][3]));
                }
                mA = redmax4(mA); mB = redmax4(mB);

                float eA[6], eB[6];
                #pragma unroll
                for (int b = 0; b < 2; b++) {
                    eA[2*b]   = __expf(d[b][0] - mA); eA[2*b+1] = __expf(d[b][1] - mA);
                    eB[2*b]   = __expf(d[b][2] - mB); eB[2*b+1] = __expf(d[b][3] - mB);
                }
                eA[4] = v2 ? __expf(d[2][0] - mA) : 0.f;
                eA[5] = v2 ? __expf(d[2][1] - mA) : 0.f;
                eB[4] = v2 ? __expf(d[2][2] - mB) : 0.f;
                eB[5] = v2 ? __expf(d[2][3] - mB) : 0.f;

                float sA = 0.f, sB = 0.f;
                #pragma unroll
                for (int i = 0; i < 6; i++) { sA += eA[i]; sB += eB[i]; }
                sA = redsum4(sA); sB = redsum4(sB);
                const float iA = 1.0f / sA, iB = 1.0f / sB;

                float m2A = 0.f, m2B = 0.f;
                #pragma unroll
                for (int i = 0; i < 6; i++) {
                    AA[i] = fmaxf(eA[i] * iA - LAMBDA, 0.f);
                    AB[i] = fmaxf(eB[i] * iB - LAMBDA, 0.f);
                    m2A = fmaxf(m2A, AA[i]); m2B = fmaxf(m2B, AB[i]);
                }
                m2A = redmax4(m2A); m2B = redmax4(m2B);

                float s2A = 0.f, s2B = 0.f;
                #pragma unroll
                for (int i = 0; i < 6; i++) {
                    const bool val = (i < 4) || v2;
                    AA[i] = val ? __expf(AA[i] - m2A) : 0.f;
                    AB[i] = val ? __expf(AB[i] - m2B) : 0.f;
                    s2A += AA[i]; s2B += AB[i];
                }
                s2A = redsum4(s2A); s2B = redsum4(s2B);
                const float i2A = 1.0f / s2A, i2B = 1.0f / s2B;
                #pragma unroll
                for (int i = 0; i < 6; i++) { AA[i] *= i2A; AB[i] *= i2B; }
            }

            // ---- att -> SMEM slot u: [16 rows][32 cols fp16], 64B rows -----
            {
                const uint32_t avA = attb + u * 1024 + rA * 64;
                const uint32_t avB = avA + 8 * 64;
                #pragma unroll
                for (int b = 0; b < 3; b++) {
                    sts32(avA + (8 * b + 2 * m) * 2, h2(AA[2*b], AA[2*b+1]));
                    sts32(avB + (8 * b + 2 * m) * 2, h2(AB[2*b], AB[2*b+1]));
                }
                sts32(avA + (24 + 2 * m) * 2, 0u);   // cols 24..31 = 0
                sts32(avB + (24 + 2 * m) * 2, 0u);
            }
            barp(barid);   // att(u) ready -> back warp
        }
    } else {
        // =================== BACK: GEMM2 + tanh + store =====================
        const int frow = (lane & 7) + ((lane & 8) ? 8 : 0);
        const int fkb  = (lane & 16) ? 16 : 0;

        for (int u = 0; u < UPP; u++) {
            barp(barid);   // wait att(u)

            uint32_t aF0[4], aF1[4];
            const uint32_t ab = attb + u * 1024 + frow * 64 + fkb;
            ldsm4(ab,      aF0[0], aF0[1], aF0[2], aF0[3]);   // k = j 0..15
            ldsm4(ab + 32, aF1[0], aF1[1], aF1[2], aF1[3]);   // k = j 16..31

            float* o0 = out + (pairRow + u * RU + rA) * FEA + 2 * m;
            #pragma unroll 4
            for (int nb = 0; nb < 256; nb++) {
                const int colb = nb * 16;
                uint32_t b00, b01, b10, b11;
                ldsm4t(jv ? btlv + (colb ^ swj) : zp, b00, b01, b10, b11);
                float e0 = 0.f, e1 = 0.f, e2 = 0.f, e3 = 0.f;
                mma16816(e0, e1, e2, e3, aF0[0], aF0[1], aF0[2], aF0[3], b00, b01);
                mma16816(e0, e1, e2, e3, aF1[0], aF1[1], aF1[2], aF1[3], b10, b11);
                *reinterpret_cast<float2*>(o0 + nb * 8) =
                    make_float2(tanh_fast(e0), tanh_fast(e1));
                *reinterpret_cast<float2*>(o0 + 8 * FEA + nb * 8) =
                    make_float2(tanh_fast(e2), tanh_fast(e3));
            }
        }
    }
}

extern "C" void kernel_launch(void* const* d_in, const int* in_sizes, int n_in,
                              void* d_out, int out_size)
{
    const float* x    = reinterpret_cast<const float*>(d_in[0]);
    const float* bank = reinterpret_cast<const float*>(d_in[1]);
    float* out        = reinterpret_cast<float*>(d_out);

    const int rows    = in_sizes[0] / FEA;       // 32768
    const int n_pairs = rows / (UPP * RU);       // 1024
    const int grid    = (n_pairs + 7) / 8;       // 128 CTAs, 8 pairs each

    cudaFuncSetAttribute(memunit_fb,
                         cudaFuncAttributeMaxDynamicSharedMemorySize, SM_TOTAL);

    memunit_fb<<<grid, NTH, SM_TOTAL>>>(x, bank, out, n_pairs);
}